// round 14
// baseline (speedup 1.0000x reference)
#include <cuda_runtime.h>

#define Bn 256
#define Nn 2048
#define An 256
#define Hn 8
#define VDn 32
#define On 256

// ---- scratch (__device__ globals; no allocations allowed) ----
__device__ float g_qavg[Bn * An];          // [B][A]
__device__ float g_qk[Bn * Hn * An];       // [B][H][A]
__device__ float g_wa[Bn * Hn * VDn];      // [B][H*VD]

__device__ __forceinline__ float tf32r(float x) {
    unsigned u;
    asm("cvt.rna.tf32.f32 %0, %1;" : "=r"(u) : "f"(x));
    return __uint_as_float(u);
}

// =====================  K1: masked mean over N  =====================
__global__ void k_qavg(const float* __restrict__ qd, const float* __restrict__ qm) {
    int b = blockIdx.y, a0 = blockIdx.x * 64, t = threadIdx.x;
    __shared__ float red[256];
    const float* mb = qm + (size_t)b * Nn;
    float ms = 0.f;
    for (int n = t; n < Nn; n += 256) ms += mb[n];
    red[t] = ms; __syncthreads();
    for (int s = 128; s; s >>= 1) { if (t < s) red[t] += red[t + s]; __syncthreads(); }
    float denom = red[0] + 1e-10f;
    __syncthreads();
    int a = a0 + (t & 63), r0 = t >> 6;
    const float* qb = qd + (size_t)b * Nn * An + a;
    float acc = 0.f;
    for (int n = r0; n < Nn; n += 4) acc += mb[n] * qb[(size_t)n * An];
    red[t] = acc; __syncthreads();
    if (t < 64)
        g_qavg[b * An + a0 + t] =
            (red[t] + red[t + 64] + red[t + 128] + red[t + 192]) / denom;
}

// =====================  K2: q projection then qk = q @ key_w^T  =====================
__global__ void k_qk(const float* __restrict__ qw, const float* __restrict__ kw) {
    int b = blockIdx.x, t = threadIdx.x;
    __shared__ float qa[256], qs[256];
    qa[t] = g_qavg[b * 256 + t];
    __syncthreads();
    float acc = 0.f;
    #pragma unroll 8
    for (int a = 0; a < 256; a++) acc += qa[a] * qw[a * 256 + t]; // t = h*32+c
    qs[t] = acc * 0.17677669529663687f; // 32^-0.5
    __syncthreads();
    // t = a
    float kr[32];
    #pragma unroll
    for (int c = 0; c < 32; c += 4) {
        float4 v = *(const float4*)(kw + t * 32 + c);
        kr[c] = v.x; kr[c + 1] = v.y; kr[c + 2] = v.z; kr[c + 3] = v.w;
    }
    #pragma unroll
    for (int h = 0; h < 8; h++) {
        float s = 0.f;
        #pragma unroll
        for (int c = 0; c < 32; c++) s += qs[h * 32 + c] * kr[c];
        g_qk[(b * 8 + h) * 256 + t] = s;
    }
}

// =====================  K3: attention per batch (logits/softmax/weighted sum)  ==========
// dyn smem: qk_s[2048] | wgt[8*2048] | mask_s[2048]  = 20480 floats = 81920 B
extern __shared__ float smem4[];
__global__ void k_attn(const float* __restrict__ md, const float* __restrict__ qm,
                       const float* __restrict__ vw) {
    float* qk_s = smem4;          // 2048 (later reused as wm[8][256])
    float* wgt = qk_s + 2048;     // 8*2048
    float* mask_s = wgt + 16384;  // 2048
    int b = blockIdx.x, t = threadIdx.x;
    int w = t >> 5, lane = t & 31;

    for (int i = t; i < 2048; i += 512) {
        qk_s[i] = g_qk[b * 2048 + i];
        mask_s[i] = qm[(size_t)b * Nn + i];
    }
    __syncthreads();
    const float* mb = md + (size_t)b * Nn * An;

    // ---- phase 1: logits[h][n] ----
    for (int n = w; n < Nn; n += 16) {
        const float* mr = mb + (size_t)n * An;
        float p[8];
        #pragma unroll
        for (int h = 0; h < 8; h++) p[h] = 0.f;
        #pragma unroll
        for (int e = 0; e < 8; e++) {
            float mv = mr[lane + 32 * e];
            #pragma unroll
            for (int h = 0; h < 8; h++) p[h] += qk_s[h * 256 + lane + 32 * e] * mv;
        }
        // reduce within quads
        #pragma unroll
        for (int h = 0; h < 8; h++) {
            p[h] += __shfl_xor_sync(0xffffffffu, p[h], 1);
            p[h] += __shfl_xor_sync(0xffffffffu, p[h], 2);
        }
        int q = lane & 3;
        float v0 = p[2 * q], v1 = p[2 * q + 1];
        #pragma unroll
        for (int d = 4; d <= 16; d <<= 1) {
            v0 += __shfl_xor_sync(0xffffffffu, v0, d);
            v1 += __shfl_xor_sync(0xffffffffu, v1, d);
        }
        if (lane < 4) {
            float mbias = 1e9f * (mask_s[n] - 1.f);
            wgt[(2 * lane) * 2048 + n] = v0 + mbias;
            wgt[(2 * lane + 1) * 2048 + n] = v1 + mbias;
        }
    }
    __syncthreads();

    // ---- softmax: warp h handles row h ----
    if (w < 8) {
        float* row = wgt + w * 2048;
        float mx = -1e30f;
        for (int n = lane; n < 2048; n += 32) mx = fmaxf(mx, row[n]);
        #pragma unroll
        for (int d = 16; d; d >>= 1) mx = fmaxf(mx, __shfl_xor_sync(0xffffffffu, mx, d));
        float sm = 0.f;
        for (int n = lane; n < 2048; n += 32) {
            float e = __expf(row[n] - mx);
            row[n] = e; sm += e;
        }
        #pragma unroll
        for (int d = 16; d; d >>= 1) sm += __shfl_xor_sync(0xffffffffu, sm, d);
        float inv = 1.f / sm;
        for (int n = lane; n < 2048; n += 32) row[n] *= inv;
    }
    __syncthreads();

    // ---- phase 2: wm[h][a] = sum_n w[h][n]*m[n][a] ----
    int a = t & 255, hb = (t >> 8) * 4;
    float acc[4] = {0.f, 0.f, 0.f, 0.f};
    #pragma unroll 4
    for (int n = 0; n < 2048; n++) {
        float mv = mb[(size_t)n * An + a];
        #pragma unroll
        for (int j = 0; j < 4; j++) acc[j] += wgt[(hb + j) * 2048 + n] * mv;
    }
    float* wm = qk_s; // safe: qk_s not read after phase 1 (sync'd)
    #pragma unroll
    for (int j = 0; j < 4; j++) wm[(hb + j) * 256 + a] = acc[j];
    __syncthreads();

    // ---- phase 3: wa[h][c] = wm @ value_w ----
    if (t < 256) {
        int h = t >> 5, c = t & 31;
        float s = 0.f;
        #pragma unroll 8
        for (int aa = 0; aa < 256; aa++) s += wm[h * 256 + aa] * vw[aa * 32 + c];
        g_wa[b * 256 + t] = s;
    }
}

// =====================  K4: fused gate-GEMM + sigmoid*wa + out-GEMM (tf32 mma)  ==========
#define TM 64
#define XS 260   // 260 % 32 == 4  -> A-frag LDS conflict-free
#define WS 264   // 264 % 32 == 8  -> B-frag LDS conflict-free
#define SMEM5_FLOATS (TM * XS + 2 * 8 * WS + 3 * 256)
#define SMEM5_BYTES (SMEM5_FLOATS * 4)

__device__ __forceinline__ void gemm_tile(const float* __restrict__ Wg,
                                          const float* Xs, float* Wsm,
                                          float acc[2][8][4],
                                          int row0, int col0, int g, int tg,
                                          int wr, int wc) {
    #pragma unroll
    for (int i = 0; i < 2; i++)
        #pragma unroll
        for (int jj = 0; jj < 8; jj++)
            #pragma unroll
            for (int r = 0; r < 4; r++) acc[i][jj][r] = 0.f;

    // preload chunk 0
    float4 p0 = *(const float4*)(Wg + wr * 256 + wc);
    float4 p1 = *(const float4*)(Wg + wr * 256 + wc + 4);
    {
        float* d = Wsm + wr * WS + wc;
        d[0] = tf32r(p0.x); d[1] = tf32r(p0.y); d[2] = tf32r(p0.z); d[3] = tf32r(p0.w);
        d[4] = tf32r(p1.x); d[5] = tf32r(p1.y); d[6] = tf32r(p1.z); d[7] = tf32r(p1.w);
    }
    __syncthreads();

    for (int kc = 0; kc < 32; kc++) {
        int cur = kc & 1;
        if (kc < 31) {
            const float* src = Wg + (size_t)(kc + 1) * 8 * 256 + wr * 256 + wc;
            p0 = *(const float4*)(src);
            p1 = *(const float4*)(src + 4);
        }
        int kb = kc * 8;
        unsigned af[2][4];
        #pragma unroll
        for (int i = 0; i < 2; i++) {
            int r0 = row0 + i * 16 + g;
            af[i][0] = __float_as_uint(Xs[r0 * XS + kb + tg]);
            af[i][1] = __float_as_uint(Xs[(r0 + 8) * XS + kb + tg]);
            af[i][2] = __float_as_uint(Xs[r0 * XS + kb + tg + 4]);
            af[i][3] = __float_as_uint(Xs[(r0 + 8) * XS + kb + tg + 4]);
        }
        const float* Wb = Wsm + cur * 8 * WS;
        #pragma unroll
        for (int jj = 0; jj < 8; jj++) {
            unsigned b0 = __float_as_uint(Wb[tg * WS + col0 + jj * 8 + g]);
            unsigned b1 = __float_as_uint(Wb[(tg + 4) * WS + col0 + jj * 8 + g]);
            #pragma unroll
            for (int i = 0; i < 2; i++) {
                asm volatile(
                    "mma.sync.aligned.m16n8k8.row.col.f32.tf32.tf32.f32 "
                    "{%0,%1,%2,%3},{%4,%5,%6,%7},{%8,%9},{%0,%1,%2,%3};"
                    : "+f"(acc[i][jj][0]), "+f"(acc[i][jj][1]),
                      "+f"(acc[i][jj][2]), "+f"(acc[i][jj][3])
                    : "r"(af[i][0]), "r"(af[i][1]), "r"(af[i][2]), "r"(af[i][3]),
                      "r"(b0), "r"(b1));
            }
        }
        if (kc < 31) {
            float* d = Wsm + (cur ^ 1) * 8 * WS + wr * WS + wc;
            d[0] = tf32r(p0.x); d[1] = tf32r(p0.y); d[2] = tf32r(p0.z); d[3] = tf32r(p0.w);
            d[4] = tf32r(p1.x); d[5] = tf32r(p1.y); d[6] = tf32r(p1.z); d[7] = tf32r(p1.w);
        }
        __syncthreads();
    }
}

extern __shared__ float sm5[];
__global__ void __launch_bounds__(256, 2)
k_fused(const float* __restrict__ qd, const float* __restrict__ gw,
        const float* __restrict__ gb, const float* __restrict__ ow,
        const float* __restrict__ ob, float* __restrict__ out) {
    float* Xs = sm5;                   // TM*XS
    float* Wsm = Xs + TM * XS;         // 2*8*WS
    float* wa_s = Wsm + 2 * 8 * WS;    // 256
    float* gb_s = wa_s + 256;          // 256
    float* ob_s = gb_s + 256;          // 256
    int t = threadIdx.x;
    int tile = blockIdx.x;
    int b = tile >> 5;                 // 32 tiles of 64 tokens per batch
    int n0 = (tile & 31) * TM;

    wa_s[t] = g_wa[b * 256 + t];
    gb_s[t] = gb[t];
    ob_s[t] = ob[t];

    // load X tile (64x256), tf32-rounded
    {
        const float* xg = qd + ((size_t)b * Nn + n0) * An;
        int cb = (t & 63) * 4;
        int rr = t >> 6;
        #pragma unroll
        for (int i = 0; i < 16; i++) {
            int r = rr + 4 * i;
            float4 v = *(const float4*)(xg + (size_t)r * An + cb);
            float* d = Xs + r * XS + cb;
            d[0] = tf32r(v.x); d[1] = tf32r(v.y); d[2] = tf32r(v.z); d[3] = tf32r(v.w);
        }
    }

    int w = t >> 5, lane = t & 31;
    int row0 = (w & 1) * 32, col0 = (w >> 1) * 64;
    int g = lane >> 2, tg = lane & 3;
    int wr = t >> 5, wc = (t & 31) * 8;

    float acc[2][8][4];

    // ---- GEMM1: X @ Wg ----
    __syncthreads();
    gemm_tile(gw, Xs, Wsm, acc, row0, col0, g, tg, wr, wc);

    // epilogue1: gate = sigmoid(acc + gb) * wa, write over Xs (all X reads sync'd)
    #pragma unroll
    for (int i = 0; i < 2; i++) {
        int r = row0 + i * 16 + g;
        #pragma unroll
        for (int jj = 0; jj < 8; jj++) {
            int c = col0 + jj * 8 + tg * 2;
            float w0 = wa_s[c], w1 = wa_s[c + 1];
            float b0 = gb_s[c], b1 = gb_s[c + 1];
            float v0 = w0 / (1.f + __expf(-(acc[i][jj][0] + b0)));
            float v1 = w1 / (1.f + __expf(-(acc[i][jj][1] + b1)));
            float v2 = w0 / (1.f + __expf(-(acc[i][jj][2] + b0)));
            float v3 = w1 / (1.f + __expf(-(acc[i][jj][3] + b1)));
            Xs[r * XS + c] = tf32r(v0);
            Xs[r * XS + c + 1] = tf32r(v1);
            Xs[(r + 8) * XS + c] = tf32r(v2);
            Xs[(r + 8) * XS + c + 1] = tf32r(v3);
        }
    }
    __syncthreads();

    // ---- GEMM2: G @ Wo ----
    gemm_tile(ow, Xs, Wsm, acc, row0, col0, g, tg, wr, wc);

    // epilogue2: + output_b, store
    float* og = out + ((size_t)b * Nn + n0) * On;
    #pragma unroll
    for (int i = 0; i < 2; i++) {
        int r = row0 + i * 16 + g;
        #pragma unroll
        for (int jj = 0; jj < 8; jj++) {
            int c = col0 + jj * 8 + tg * 2;
            float2 u0 = make_float2(acc[i][jj][0] + ob_s[c], acc[i][jj][1] + ob_s[c + 1]);
            float2 u1 = make_float2(acc[i][jj][2] + ob_s[c], acc[i][jj][3] + ob_s[c + 1]);
            *(float2*)(og + (size_t)r * On + c) = u0;
            *(float2*)(og + (size_t)(r + 8) * On + c) = u1;
        }
    }
}

// =====================  launch  =====================
extern "C" void kernel_launch(void* const* d_in, const int* in_sizes, int n_in,
                              void* d_out, int out_size) {
    (void)in_sizes; (void)n_in; (void)out_size;
    const float* qd = (const float*)d_in[0];   // q_data [B,N,A]
    const float* md = (const float*)d_in[1];   // m_data [B,N,M]
    const float* qm = (const float*)d_in[2];   // q_mask [B,N,1]
    const float* qw = (const float*)d_in[4];   // query_w [A,H,KD]
    const float* kw = (const float*)d_in[5];   // key_w [M,KD]
    const float* vw = (const float*)d_in[6];   // value_w [M,VD]
    const float* gw = (const float*)d_in[7];   // gating_w [A,H,VD]
    const float* gb = (const float*)d_in[8];   // gating_b [H,VD]
    const float* ow = (const float*)d_in[9];   // output_w [H,VD,O]
    const float* ob = (const float*)d_in[10];  // output_b [O]
    float* out = (float*)d_out;

    cudaFuncSetAttribute(k_attn, cudaFuncAttributeMaxDynamicSharedMemorySize, 81920);
    cudaFuncSetAttribute(k_fused, cudaFuncAttributeMaxDynamicSharedMemorySize, SMEM5_BYTES);

    k_qavg<<<dim3(4, 256), 256>>>(qd, qm);
    k_qk<<<256, 256>>>(qw, kw);
    k_attn<<<256, 512, 81920>>>(md, qm, vw);
    k_fused<<<8192, 256, SMEM5_BYTES>>>(qd, gw, gb, ow, ob, out);
}